// round 1
// baseline (speedup 1.0000x reference)
#include <cuda_runtime.h>

#define NN 100000
#define NE 3200000
#define F1 16

// ---- scratch (static device allocations; no cudaMalloc allowed) ----
__device__ float g_h0[NN * F1];    // x @ W1
__device__ float g_out1[NN * F1];  // layer-1 aggregation
__device__ float g_deg[NN];
__device__ float g_dinv[NN];
__device__ float g_g[NN];          // relu(out1+b1) @ W2
__device__ float g_out2[NN];       // layer-2 aggregation
__device__ int   g_is64;           // edge_index dtype flag

// ---------------- dtype detection (int64 vs int32 edge_index) -------------
__global__ void k_detect(const unsigned int* __restrict__ ei32) {
    if (threadIdx.x == 0 && blockIdx.x == 0) {
        int ok = 1;
        #pragma unroll 1
        for (int k = 0; k < 64; k++) {
            if (ei32[2 * k + 1] != 0u) { ok = 0; break; }
        }
        g_is64 = ok;
    }
}

__device__ __forceinline__ int load_idx(const void* ei, long long pos, int is64) {
    if (is64) return (int)__ldg((const long long*)ei + pos);
    return __ldg((const int*)ei + pos);
}

// ---------------- init: zero accumulators, deg = 1 (self-loop) ------------
__global__ void k_init() {
    int i = blockIdx.x * blockDim.x + threadIdx.x;
    if (i < NN * F1) g_out1[i] = 0.0f;
    if (i < NN) { g_deg[i] = 1.0f; g_out2[i] = 0.0f; }
}

// ---------------- degree accumulation --------------------------------------
__global__ void k_deg(const void* __restrict__ ei) {
    int e = blockIdx.x * blockDim.x + threadIdx.x;
    if (e >= NE) return;
    int is64 = g_is64;
    int c = load_idx(ei, (long long)NE + e, is64);
    atomicAdd(&g_deg[c], 1.0f);
}

__global__ void k_dinv() {
    int i = blockIdx.x * blockDim.x + threadIdx.x;
    if (i < NN) g_dinv[i] = rsqrtf(g_deg[i]);
}

// ---------------- GEMM1: h0 = x @ W1  (128 -> 16) --------------------------
// 4 nodes per thread; W1 broadcast from shared; fp32 FMA.
#define GEMM_NPT 4
#define GEMM_TPB 128
__global__ __launch_bounds__(GEMM_TPB) void k_gemm1(
    const float* __restrict__ x, const float* __restrict__ W1) {
    __shared__ float ws[128 * F1];
    for (int t = threadIdx.x; t < 128 * F1; t += GEMM_TPB) ws[t] = W1[t];
    __syncthreads();

    int nbase = blockIdx.x * (GEMM_TPB * GEMM_NPT) + threadIdx.x;
    float acc[GEMM_NPT][F1];
    #pragma unroll
    for (int nn = 0; nn < GEMM_NPT; nn++)
        #pragma unroll
        for (int j = 0; j < F1; j++) acc[nn][j] = 0.0f;

    #pragma unroll 4
    for (int k4 = 0; k4 < 32; k4++) {
        float4 xr[GEMM_NPT];
        #pragma unroll
        for (int nn = 0; nn < GEMM_NPT; nn++) {
            int node = nbase + nn * GEMM_TPB;
            if (node < NN)
                xr[nn] = __ldg((const float4*)(x + (long long)node * 128) + k4);
            else
                xr[nn] = make_float4(0.f, 0.f, 0.f, 0.f);
        }
        #pragma unroll
        for (int kk = 0; kk < 4; kk++) {
            float xs[GEMM_NPT];
            #pragma unroll
            for (int nn = 0; nn < GEMM_NPT; nn++) {
                const float* xa = (const float*)&xr[nn];
                xs[nn] = xa[kk];
            }
            #pragma unroll
            for (int j = 0; j < F1; j++) {
                float wv = ws[(k4 * 4 + kk) * F1 + j];
                #pragma unroll
                for (int nn = 0; nn < GEMM_NPT; nn++)
                    acc[nn][j] = fmaf(xs[nn], wv, acc[nn][j]);
            }
        }
    }
    #pragma unroll
    for (int nn = 0; nn < GEMM_NPT; nn++) {
        int node = nbase + nn * GEMM_TPB;
        if (node < NN) {
            float4* o = (float4*)(g_h0 + (long long)node * F1);
            o[0] = make_float4(acc[nn][0], acc[nn][1], acc[nn][2], acc[nn][3]);
            o[1] = make_float4(acc[nn][4], acc[nn][5], acc[nn][6], acc[nn][7]);
            o[2] = make_float4(acc[nn][8], acc[nn][9], acc[nn][10], acc[nn][11]);
            o[3] = make_float4(acc[nn][12], acc[nn][13], acc[nn][14], acc[nn][15]);
        }
    }
}

// ---------------- Layer-1 scatter: out1[col] += h0[row] * norm -------------
__device__ __forceinline__ void red_v4(float* addr, float a, float b, float c, float d) {
    asm volatile("red.global.add.v4.f32 [%0], {%1,%2,%3,%4};"
                 :: "l"(addr), "f"(a), "f"(b), "f"(c), "f"(d) : "memory");
}

__global__ void k_scatter1(const void* __restrict__ ei) {
    int e = blockIdx.x * blockDim.x + threadIdx.x;
    if (e >= NE + NN) return;
    int is64 = g_is64;
    int r, c; float n;
    if (e < NE) {
        r = load_idx(ei, e, is64);
        c = load_idx(ei, (long long)NE + e, is64);
        n = __ldg(&g_dinv[r]) * __ldg(&g_dinv[c]);
    } else {
        r = c = e - NE;
        float d = __ldg(&g_dinv[r]);
        n = d * d;
    }
    const float4* h = (const float4*)(g_h0 + (long long)r * F1);
    float* o = g_out1 + (long long)c * F1;
    #pragma unroll
    for (int q = 0; q < 4; q++) {
        float4 v = __ldg(h + q);
        red_v4(o + q * 4, v.x * n, v.y * n, v.z * n, v.w * n);
    }
}

// ---------------- act1: g = relu(out1 + b1) @ W2 ----------------------------
__global__ void k_act1(const float* __restrict__ b1, const float* __restrict__ W2) {
    int i = blockIdx.x * blockDim.x + threadIdx.x;
    if (i >= NN) return;
    const float* o = g_out1 + (long long)i * F1;
    float s = 0.0f;
    #pragma unroll
    for (int j = 0; j < F1; j++) {
        float v = o[j] + __ldg(&b1[j]);
        v = fmaxf(v, 0.0f);
        s = fmaf(v, __ldg(&W2[j]), s);
    }
    g_g[i] = s;
}

// ---------------- Layer-2 scatter: out2[col] += g[row] * norm --------------
__global__ void k_scatter2(const void* __restrict__ ei) {
    int e = blockIdx.x * blockDim.x + threadIdx.x;
    if (e >= NE + NN) return;
    int is64 = g_is64;
    int r, c; float n;
    if (e < NE) {
        r = load_idx(ei, e, is64);
        c = load_idx(ei, (long long)NE + e, is64);
        n = __ldg(&g_dinv[r]) * __ldg(&g_dinv[c]);
    } else {
        r = c = e - NE;
        float d = __ldg(&g_dinv[r]);
        n = d * d;
    }
    float msg = __ldg(&g_g[r]) * n;
    asm volatile("red.global.add.f32 [%0], %1;" :: "l"(g_out2 + c), "f"(msg) : "memory");
}

// ---------------- final: sigmoid(out2 + b2) ---------------------------------
__global__ void k_final(const float* __restrict__ b2, float* __restrict__ out) {
    int i = blockIdx.x * blockDim.x + threadIdx.x;
    if (i >= NN) return;
    float v = g_out2[i] + __ldg(&b2[0]);
    out[i] = 1.0f / (1.0f + __expf(-v));
}

// ---------------- launch ----------------------------------------------------
extern "C" void kernel_launch(void* const* d_in, const int* in_sizes, int n_in,
                              void* d_out, int out_size) {
    const float* x  = (const float*)d_in[0];
    const void*  ei = d_in[1];
    const float* W1 = (const float*)d_in[2];
    const float* b1 = (const float*)d_in[3];
    const float* W2 = (const float*)d_in[4];
    const float* b2 = (const float*)d_in[5];
    float* out = (float*)d_out;

    k_detect<<<1, 32>>>((const unsigned int*)ei);
    k_init<<<(NN * F1 + 255) / 256, 256>>>();
    k_deg<<<(NE + 255) / 256, 256>>>(ei);
    k_dinv<<<(NN + 255) / 256, 256>>>();
    k_gemm1<<<(NN + GEMM_TPB * GEMM_NPT - 1) / (GEMM_TPB * GEMM_NPT), GEMM_TPB>>>(x, W1);
    k_scatter1<<<(NE + NN + 255) / 256, 256>>>(ei);
    k_act1<<<(NN + 255) / 256, 256>>>(b1, W2);
    k_scatter2<<<(NE + NN + 255) / 256, 256>>>(ei);
    k_final<<<(NN + 255) / 256, 256>>>(b2, out);
}

// round 2
// speedup vs baseline: 1.1373x; 1.1373x over previous
#include <cuda_runtime.h>

#define NN 100000
#define NE 3200000
#define F1 16

#define SCAN_B 256
#define SCAN_NBLK ((NN + SCAN_B - 1) / SCAN_B)   // 391

// ---- static device scratch (no cudaMalloc allowed) ----
__device__ float g_h0[NN * F1];      // x @ W1
__device__ float g_g[NN];            // relu(out1+b1) @ W2
__device__ int   g_len[NN];          // incoming-edge count (excl self loop)
__device__ int   g_rowptr[NN + 1];
__device__ float g_dinv[NN];
__device__ int   g_er[NE];           // src per edge
__device__ int   g_ec[NE];           // dst per edge
__device__ int   g_pw[NE];           // position within dst's row
__device__ int2  g_csr[NE];          // {src, norm bits} sorted by dst
__device__ int   g_bsum[SCAN_NBLK];
__device__ int   g_boff[SCAN_NBLK];
__device__ int   g_is64;

// ---------------- dtype detection (int64 vs int32 edge_index) -------------
__global__ void k_detect(const unsigned int* __restrict__ ei32) {
    if (threadIdx.x == 0) {
        int ok = 1;
        #pragma unroll 1
        for (int k = 0; k < 64; k++)
            if (ei32[2 * k + 1] != 0u) { ok = 0; break; }
        g_is64 = ok;
    }
}

__device__ __forceinline__ int load_idx(const void* ei, long long pos, int is64) {
    if (is64) return (int)__ldg((const long long*)ei + pos);
    return __ldg((const int*)ei + pos);
}

// ---------------- zero len ----------------
__global__ void k_zero() {
    int i = blockIdx.x * blockDim.x + threadIdx.x;
    if (i < NN) g_len[i] = 0;
}

// ---------------- pack edges + count (single atomic pass) -----------------
__global__ void k_pack(const void* __restrict__ ei) {
    int e = blockIdx.x * blockDim.x + threadIdx.x;
    if (e >= NE) return;
    int is64 = g_is64;
    int r = load_idx(ei, e, is64);
    int c = load_idx(ei, (long long)NE + e, is64);
    g_er[e] = r;
    g_ec[e] = c;
    g_pw[e] = atomicAdd(&g_len[c], 1);   // returned old value = CSR slot
}

// ---------------- 3-phase exclusive scan of g_len -> g_rowptr -------------
__global__ void k_scan1() {
    __shared__ int s[SCAN_B];
    int t = threadIdx.x;
    int i = blockIdx.x * SCAN_B + t;
    int v = (i < NN) ? g_len[i] : 0;
    s[t] = v;
    __syncthreads();
    #pragma unroll
    for (int off = 1; off < SCAN_B; off <<= 1) {
        int a = (t >= off) ? s[t - off] : 0;
        __syncthreads();
        s[t] += a;
        __syncthreads();
    }
    if (i < NN) g_rowptr[i] = s[t] - v;        // local exclusive
    if (t == SCAN_B - 1) g_bsum[blockIdx.x] = s[t];
}

__global__ void k_scan2() {
    __shared__ int s[512];
    int t = threadIdx.x;
    s[t] = (t < SCAN_NBLK) ? g_bsum[t] : 0;
    __syncthreads();
    #pragma unroll
    for (int off = 1; off < 512; off <<= 1) {
        int a = (t >= off) ? s[t - off] : 0;
        __syncthreads();
        s[t] += a;
        __syncthreads();
    }
    if (t < SCAN_NBLK) g_boff[t] = s[t] - g_bsum[t];  // exclusive
}

__global__ void k_scan3() {
    int i = blockIdx.x * blockDim.x + threadIdx.x;
    if (i < NN) {
        g_rowptr[i] += g_boff[i / SCAN_B];
        g_dinv[i] = rsqrtf((float)g_len[i] + 1.0f);
    }
    if (i == 0) g_rowptr[NN] = NE;
}

// ---------------- fill CSR: {src, norm} per slot (no atomics) --------------
__global__ void k_fill() {
    int e = blockIdx.x * blockDim.x + threadIdx.x;
    if (e >= NE) return;
    int r = g_er[e];
    int c = g_ec[e];
    int pos = g_rowptr[c] + g_pw[e];
    float nrm = __ldg(&g_dinv[r]) * __ldg(&g_dinv[c]);
    g_csr[pos] = make_int2(r, __float_as_int(nrm));
}

// ---------------- GEMM1: h0 = x @ W1  (128 -> 16) --------------------------
#define GEMM_NPT 4
#define GEMM_TPB 128
__global__ __launch_bounds__(GEMM_TPB) void k_gemm1(
    const float* __restrict__ x, const float* __restrict__ W1) {
    __shared__ float ws[128 * F1];
    for (int t = threadIdx.x; t < 128 * F1; t += GEMM_TPB) ws[t] = W1[t];
    __syncthreads();

    int nbase = blockIdx.x * (GEMM_TPB * GEMM_NPT) + threadIdx.x;
    float acc[GEMM_NPT][F1];
    #pragma unroll
    for (int nn = 0; nn < GEMM_NPT; nn++)
        #pragma unroll
        for (int j = 0; j < F1; j++) acc[nn][j] = 0.0f;

    #pragma unroll 4
    for (int k4 = 0; k4 < 32; k4++) {
        float4 xr[GEMM_NPT];
        #pragma unroll
        for (int nn = 0; nn < GEMM_NPT; nn++) {
            int node = nbase + nn * GEMM_TPB;
            xr[nn] = (node < NN)
                ? __ldg((const float4*)(x + (long long)node * 128) + k4)
                : make_float4(0.f, 0.f, 0.f, 0.f);
        }
        #pragma unroll
        for (int kk = 0; kk < 4; kk++) {
            #pragma unroll
            for (int j = 0; j < F1; j++) {
                float wv = ws[(k4 * 4 + kk) * F1 + j];
                #pragma unroll
                for (int nn = 0; nn < GEMM_NPT; nn++) {
                    const float* xa = (const float*)&xr[nn];
                    acc[nn][j] = fmaf(xa[kk], wv, acc[nn][j]);
                }
            }
        }
    }
    #pragma unroll
    for (int nn = 0; nn < GEMM_NPT; nn++) {
        int node = nbase + nn * GEMM_TPB;
        if (node < NN) {
            float4* o = (float4*)(g_h0 + (long long)node * F1);
            o[0] = make_float4(acc[nn][0], acc[nn][1], acc[nn][2], acc[nn][3]);
            o[1] = make_float4(acc[nn][4], acc[nn][5], acc[nn][6], acc[nn][7]);
            o[2] = make_float4(acc[nn][8], acc[nn][9], acc[nn][10], acc[nn][11]);
            o[3] = make_float4(acc[nn][12], acc[nn][13], acc[nn][14], acc[nn][15]);
        }
    }
}

// ---------------- gather1 (fused: aggregate + b1 + relu + @W2) -------------
// one warp per node; half-warp per edge; lane&15 = feature index
__global__ __launch_bounds__(256) void k_gather1(
    const float* __restrict__ b1, const float* __restrict__ W2) {
    int node = (blockIdx.x * blockDim.x + threadIdx.x) >> 5;
    int lane = threadIdx.x & 31;
    if (node >= NN) return;
    int beg = g_rowptr[node];
    int end = g_rowptr[node + 1];
    int half = lane >> 4;
    int f = lane & 15;

    float acc = 0.0f;
    for (int p = beg + half; p < end; p += 2) {
        int2 sn = __ldg(&g_csr[p]);
        acc = fmaf(__ldg(&g_h0[sn.x * F1 + f]), __int_as_float(sn.y), acc);
    }
    // self loop (weight dinv^2)
    if (half == 0) {
        float dc = __ldg(&g_dinv[node]);
        acc = fmaf(__ldg(&g_h0[node * F1 + f]), dc * dc, acc);
    }
    acc += __shfl_xor_sync(0xffffffffu, acc, 16);
    // acc = out1[node][f]; fuse bias+relu+W2
    float v = fmaxf(acc + __ldg(&b1[f]), 0.0f) * __ldg(&W2[f]);
    v += __shfl_xor_sync(0xffffffffu, v, 8);
    v += __shfl_xor_sync(0xffffffffu, v, 4);
    v += __shfl_xor_sync(0xffffffffu, v, 2);
    v += __shfl_xor_sync(0xffffffffu, v, 1);
    if (lane == 0) g_g[node] = v;
}

// ---------------- gather2 (fused: aggregate + b2 + sigmoid) ----------------
__global__ __launch_bounds__(256) void k_gather2(
    const float* __restrict__ b2, float* __restrict__ out) {
    int node = (blockIdx.x * blockDim.x + threadIdx.x) >> 5;
    int lane = threadIdx.x & 31;
    if (node >= NN) return;
    int beg = g_rowptr[node];
    int end = g_rowptr[node + 1];

    float acc = 0.0f;
    for (int p = beg + lane; p < end; p += 32) {
        int2 sn = __ldg(&g_csr[p]);
        acc = fmaf(__ldg(&g_g[sn.x]), __int_as_float(sn.y), acc);
    }
    if (lane == 0) {
        float dc = __ldg(&g_dinv[node]);
        acc = fmaf(__ldg(&g_g[node]), dc * dc, acc);
    }
    acc += __shfl_xor_sync(0xffffffffu, acc, 16);
    acc += __shfl_xor_sync(0xffffffffu, acc, 8);
    acc += __shfl_xor_sync(0xffffffffu, acc, 4);
    acc += __shfl_xor_sync(0xffffffffu, acc, 2);
    acc += __shfl_xor_sync(0xffffffffu, acc, 1);
    if (lane == 0) {
        float v = acc + __ldg(&b2[0]);
        out[node] = 1.0f / (1.0f + __expf(-v));
    }
}

// ---------------- launch ----------------------------------------------------
extern "C" void kernel_launch(void* const* d_in, const int* in_sizes, int n_in,
                              void* d_out, int out_size) {
    const float* x  = (const float*)d_in[0];
    const void*  ei = d_in[1];
    const float* W1 = (const float*)d_in[2];
    const float* b1 = (const float*)d_in[3];
    const float* W2 = (const float*)d_in[4];
    const float* b2 = (const float*)d_in[5];
    float* out = (float*)d_out;

    k_detect<<<1, 32>>>((const unsigned int*)ei);
    k_zero<<<(NN + 255) / 256, 256>>>();
    k_pack<<<(NE + 255) / 256, 256>>>(ei);
    k_scan1<<<SCAN_NBLK, SCAN_B>>>();
    k_scan2<<<1, 512>>>();
    k_scan3<<<(NN + 255) / 256, 256>>>();
    k_fill<<<(NE + 255) / 256, 256>>>();
    k_gemm1<<<(NN + GEMM_TPB * GEMM_NPT - 1) / (GEMM_TPB * GEMM_NPT), GEMM_TPB>>>(x, W1);
    k_gather1<<<(NN * 32 + 255) / 256, 256>>>(b1, W2);
    k_gather2<<<(NN * 32 + 255) / 256, 256>>>(b2, out);
}

// round 3
// speedup vs baseline: 1.3434x; 1.1812x over previous
#include <cuda_runtime.h>
#include <cuda_fp16.h>

#define NN 100000
#define NE 3200000
#define F1 16

#define SCAN_B 512
#define SCAN_NBLK ((NN + SCAN_B - 1) / SCAN_B)   // 196

// ---- static device scratch (no cudaMalloc allowed) ----
__device__ __half g_h0s[NN * F1];    // (x @ W1) * dinv[node], fp16
__device__ float  g_gs[NN];          // g[node] * dinv[node]
__device__ int    g_len[NN];
__device__ int    g_rowptr[NN + 1];
__device__ float  g_dinv[NN];
__device__ int2   g_erc[NE];         // packed (row, col)
__device__ int    g_pw[NE];          // slot within dst row
__device__ int    g_csr[NE];         // src only, grouped by dst
__device__ int    g_bsum[SCAN_NBLK];
__device__ int    g_boff[SCAN_NBLK];
__device__ int    g_is64;

// ---------------- init: zero len + dtype detect ----------------------------
__global__ void k_init(const unsigned int* __restrict__ ei32) {
    int i = blockIdx.x * blockDim.x + threadIdx.x;
    if (i < NN) g_len[i] = 0;
    if (i == 0) {
        int ok = 1;
        #pragma unroll 1
        for (int k = 0; k < 64; k++)
            if (ei32[2 * k + 1] != 0u) { ok = 0; break; }
        g_is64 = ok;
    }
}

__device__ __forceinline__ int load_idx(const void* ei, long long pos, int is64) {
    if (is64) return (int)__ldg((const long long*)ei + pos);
    return __ldg((const int*)ei + pos);
}

// ---------------- pack edges + count (single atomic-return pass) -----------
__global__ void k_pack(const void* __restrict__ ei) {
    int e = blockIdx.x * blockDim.x + threadIdx.x;
    if (e >= NE) return;
    int is64 = g_is64;
    int r = load_idx(ei, e, is64);
    int c = load_idx(ei, (long long)NE + e, is64);
    g_erc[e] = make_int2(r, c);
    g_pw[e] = atomicAdd(&g_len[c], 1);
}

// ---------------- warp-shuffle block scans ---------------------------------
__global__ __launch_bounds__(SCAN_B) void k_scan1() {
    int t = threadIdx.x, lane = t & 31, wid = t >> 5;
    int i = blockIdx.x * SCAN_B + t;
    int v = (i < NN) ? g_len[i] : 0;
    int s = v;
    #pragma unroll
    for (int off = 1; off < 32; off <<= 1) {
        int n = __shfl_up_sync(0xffffffffu, s, off);
        if (lane >= off) s += n;
    }
    __shared__ int wsum[16];
    if (lane == 31) wsum[wid] = s;
    __syncthreads();
    if (wid == 0 && lane < 16) {
        int ws = wsum[lane], sc = ws;
        #pragma unroll
        for (int off = 1; off < 16; off <<= 1) {
            int n = __shfl_up_sync(0xffffu, sc, off);
            if (lane >= off) sc += n;
        }
        wsum[lane] = sc - ws;   // exclusive warp offsets
    }
    __syncthreads();
    int incl = s + wsum[wid];
    if (i < NN) g_rowptr[i] = incl - v;
    if (t == SCAN_B - 1) g_bsum[blockIdx.x] = incl;
}

__global__ __launch_bounds__(256) void k_scan2() {
    int t = threadIdx.x, lane = t & 31, wid = t >> 5;
    int v = (t < SCAN_NBLK) ? g_bsum[t] : 0;
    int s = v;
    #pragma unroll
    for (int off = 1; off < 32; off <<= 1) {
        int n = __shfl_up_sync(0xffffffffu, s, off);
        if (lane >= off) s += n;
    }
    __shared__ int wsum[8];
    if (lane == 31) wsum[wid] = s;
    __syncthreads();
    if (wid == 0 && lane < 8) {
        int ws = wsum[lane], sc = ws;
        #pragma unroll
        for (int off = 1; off < 8; off <<= 1) {
            int n = __shfl_up_sync(0xffu, sc, off);
            if (lane >= off) sc += n;
        }
        wsum[lane] = sc - ws;
    }
    __syncthreads();
    if (t < SCAN_NBLK) g_boff[t] = s + wsum[wid] - v;   // exclusive
}

__global__ void k_scan3() {
    int i = blockIdx.x * blockDim.x + threadIdx.x;
    if (i < NN) {
        g_rowptr[i] += g_boff[i / SCAN_B];
        g_dinv[i] = rsqrtf((float)g_len[i] + 1.0f);
    }
    if (i == 0) g_rowptr[NN] = NE;
}

// ---------------- fill CSR: src only (no atomics, no norm) -----------------
__global__ void k_fill() {
    int e = blockIdx.x * blockDim.x + threadIdx.x;
    if (e >= NE) return;
    int2 rc = g_erc[e];
    g_csr[g_rowptr[rc.y] + g_pw[e]] = rc.x;
}

// ---------------- GEMM1: h0s = (x @ W1) * dinv, fp16 -----------------------
#define GEMM_NPT 4
#define GEMM_TPB 128
__global__ __launch_bounds__(GEMM_TPB) void k_gemm1(
    const float* __restrict__ x, const float* __restrict__ W1) {
    __shared__ float ws[128 * F1];
    for (int t = threadIdx.x; t < 128 * F1; t += GEMM_TPB) ws[t] = W1[t];
    __syncthreads();

    int nbase = blockIdx.x * (GEMM_TPB * GEMM_NPT) + threadIdx.x;
    float acc[GEMM_NPT][F1];
    #pragma unroll
    for (int nn = 0; nn < GEMM_NPT; nn++)
        #pragma unroll
        for (int j = 0; j < F1; j++) acc[nn][j] = 0.0f;

    #pragma unroll 4
    for (int k4 = 0; k4 < 32; k4++) {
        float4 xr[GEMM_NPT];
        #pragma unroll
        for (int nn = 0; nn < GEMM_NPT; nn++) {
            int node = nbase + nn * GEMM_TPB;
            xr[nn] = (node < NN)
                ? __ldg((const float4*)(x + (long long)node * 128) + k4)
                : make_float4(0.f, 0.f, 0.f, 0.f);
        }
        #pragma unroll
        for (int kk = 0; kk < 4; kk++) {
            #pragma unroll
            for (int j = 0; j < F1; j++) {
                float wv = ws[(k4 * 4 + kk) * F1 + j];
                #pragma unroll
                for (int nn = 0; nn < GEMM_NPT; nn++) {
                    const float* xa = (const float*)&xr[nn];
                    acc[nn][j] = fmaf(xa[kk], wv, acc[nn][j]);
                }
            }
        }
    }
    #pragma unroll
    for (int nn = 0; nn < GEMM_NPT; nn++) {
        int node = nbase + nn * GEMM_TPB;
        if (node < NN) {
            float di = __ldg(&g_dinv[node]);
            union { __half2 h2[4]; uint4 u; } pk0, pk1;
            #pragma unroll
            for (int j = 0; j < 4; j++)
                pk0.h2[j] = __floats2half2_rn(acc[nn][2*j] * di, acc[nn][2*j+1] * di);
            #pragma unroll
            for (int j = 0; j < 4; j++)
                pk1.h2[j] = __floats2half2_rn(acc[nn][8+2*j] * di, acc[nn][9+2*j] * di);
            uint4* o = (uint4*)(g_h0s + (long long)node * F1);
            o[0] = pk0.u;
            o[1] = pk1.u;
        }
    }
}

// ---------------- gather1: gs[n] = dinv[n] * (relu(dinv[n]*Σ h0s + b1) @ W2)
// one warp per node; half-warp per edge; lane&15 = feature
__global__ __launch_bounds__(256) void k_gather1(
    const float* __restrict__ b1, const float* __restrict__ W2) {
    int node = (blockIdx.x * blockDim.x + threadIdx.x) >> 5;
    int lane = threadIdx.x & 31;
    if (node >= NN) return;
    int beg = g_rowptr[node];
    int end = g_rowptr[node + 1];
    int half = lane >> 4;
    int f = lane & 15;

    // self loop contribution (once, on half 0)
    float acc = (half == 0) ? __half2float(__ldg(&g_h0s[node * F1 + f])) : 0.0f;

    int p = beg + half;
    for (; p + 2 < end; p += 4) {
        int s0 = __ldg(&g_csr[p]);
        int s1 = __ldg(&g_csr[p + 2]);
        float a0 = __half2float(__ldg(&g_h0s[s0 * F1 + f]));
        float a1 = __half2float(__ldg(&g_h0s[s1 * F1 + f]));
        acc += a0 + a1;
    }
    if (p < end) {
        int s0 = __ldg(&g_csr[p]);
        acc += __half2float(__ldg(&g_h0s[s0 * F1 + f]));
    }
    acc += __shfl_xor_sync(0xffffffffu, acc, 16);

    float di = __ldg(&g_dinv[node]);
    float v = fmaxf(fmaf(acc, di, __ldg(&b1[f])), 0.0f) * __ldg(&W2[f]);
    v += __shfl_xor_sync(0xffffffffu, v, 8);
    v += __shfl_xor_sync(0xffffffffu, v, 4);
    v += __shfl_xor_sync(0xffffffffu, v, 2);
    v += __shfl_xor_sync(0xffffffffu, v, 1);
    if (lane == 0) g_gs[node] = v * di;
}

// ---------------- gather2: out = sigmoid(dinv*(Σ gs + gs[self]) + b2) -------
__global__ __launch_bounds__(256) void k_gather2(
    const float* __restrict__ b2, float* __restrict__ out) {
    int node = (blockIdx.x * blockDim.x + threadIdx.x) >> 5;
    int lane = threadIdx.x & 31;
    if (node >= NN) return;
    int beg = g_rowptr[node];
    int end = g_rowptr[node + 1];

    float acc = 0.0f;
    int p = beg + lane;
    for (; p + 32 < end; p += 64) {
        int s0 = __ldg(&g_csr[p]);
        int s1 = __ldg(&g_csr[p + 32]);
        acc += __ldg(&g_gs[s0]) + __ldg(&g_gs[s1]);
    }
    if (p < end) acc += __ldg(&g_gs[__ldg(&g_csr[p])]);
    if (lane == 0) acc += __ldg(&g_gs[node]);   // self loop

    acc += __shfl_xor_sync(0xffffffffu, acc, 16);
    acc += __shfl_xor_sync(0xffffffffu, acc, 8);
    acc += __shfl_xor_sync(0xffffffffu, acc, 4);
    acc += __shfl_xor_sync(0xffffffffu, acc, 2);
    acc += __shfl_xor_sync(0xffffffffu, acc, 1);
    if (lane == 0) {
        float v = fmaf(acc, __ldg(&g_dinv[node]), __ldg(&b2[0]));
        out[node] = 1.0f / (1.0f + __expf(-v));
    }
}

// ---------------- launch ----------------------------------------------------
extern "C" void kernel_launch(void* const* d_in, const int* in_sizes, int n_in,
                              void* d_out, int out_size) {
    const float* x  = (const float*)d_in[0];
    const void*  ei = d_in[1];
    const float* W1 = (const float*)d_in[2];
    const float* b1 = (const float*)d_in[3];
    const float* W2 = (const float*)d_in[4];
    const float* b2 = (const float*)d_in[5];
    float* out = (float*)d_out;

    k_init<<<(NN + 255) / 256, 256>>>((const unsigned int*)ei);
    k_pack<<<(NE + 255) / 256, 256>>>(ei);
    k_scan1<<<SCAN_NBLK, SCAN_B>>>();
    k_scan2<<<1, 256>>>();
    k_scan3<<<(NN + 255) / 256, 256>>>();
    k_fill<<<(NE + 255) / 256, 256>>>();
    k_gemm1<<<(NN + GEMM_TPB * GEMM_NPT - 1) / (GEMM_TPB * GEMM_NPT), GEMM_TPB>>>(x, W1);
    k_gather1<<<(NN * 32 + 255) / 256, 256>>>(b1, W2);
    k_gather2<<<(NN * 32 + 255) / 256, 256>>>(b2, out);
}

// round 4
// speedup vs baseline: 1.4252x; 1.0609x over previous
#include <cuda_runtime.h>
#include <cuda_fp16.h>

#define NN 100000
#define NE 3200000
#define F1 16

#define SCAN_T 512
#define NTILES ((NN + SCAN_T - 1) / SCAN_T)   // 196

#define GEMM_BLKS 196          // 196 * 512 nodes (256 thr * NPT 2)
#define CNT_BLKS ((NE + 255) / 256)   // 12500

// ---- static device scratch (no cudaMalloc allowed) ----
__device__ __half g_h0s[NN * F1];    // (x @ W1) * dinv[node], fp16
__device__ float  g_gs[NN];          // layer-1 output * dinv[node]
__device__ int    g_rowptr[NN + 1];
__device__ int    g_cursor[NN];
__device__ float  g_dinv[NN];
__device__ int    g_csr[NE];         // src grouped by dst
__device__ int    g_is64;

// contiguous so ONE memset clears everything
__device__ struct {
    int len[NN];
    unsigned long long state[NTILES];
    int ticket;
} g_cnt;

// ---------------- dtype detect (int64 vs int32 edge_index) -----------------
__global__ void k_detect(const unsigned int* __restrict__ ei32) {
    if (threadIdx.x == 0) {
        int ok = 1;
        #pragma unroll 1
        for (int k = 0; k < 64; k++)
            if (ei32[2 * k + 1] != 0u) { ok = 0; break; }
        g_is64 = ok;
    }
}

// ---------------- fused: edge counting + GEMM1 (independent work) ----------
// blocks [0, GEMM_BLKS): h0s = fp16(x @ W1), unscaled
// blocks [GEMM_BLKS, GEMM_BLKS+CNT_BLKS): count incoming edges
__global__ __launch_bounds__(256) void k_count_gemm(
    const float* __restrict__ x, const float* __restrict__ W1,
    const void* __restrict__ ei) {
    if (blockIdx.x >= GEMM_BLKS) {
        int e = (blockIdx.x - GEMM_BLKS) * 256 + threadIdx.x;
        if (e >= NE) return;
        int c = g_is64 ? ((const int2*)ei)[NE + e].x
                       : __ldg((const int*)ei + NE + e);
        atomicAdd(&g_cnt.len[c], 1);   // no return use -> RED
        return;
    }
    __shared__ float ws[128 * F1];
    for (int t = threadIdx.x; t < 128 * F1; t += 256) ws[t] = W1[t];
    __syncthreads();

    int nbase = blockIdx.x * 512 + threadIdx.x;
    float acc[2][F1];
    #pragma unroll
    for (int nn = 0; nn < 2; nn++)
        #pragma unroll
        for (int j = 0; j < F1; j++) acc[nn][j] = 0.0f;

    #pragma unroll 4
    for (int k4 = 0; k4 < 32; k4++) {
        float4 xr[2];
        #pragma unroll
        for (int nn = 0; nn < 2; nn++) {
            int node = nbase + nn * 256;
            xr[nn] = (node < NN)
                ? __ldg((const float4*)(x + (long long)node * 128) + k4)
                : make_float4(0.f, 0.f, 0.f, 0.f);
        }
        #pragma unroll
        for (int kk = 0; kk < 4; kk++) {
            #pragma unroll
            for (int j = 0; j < F1; j++) {
                float wv = ws[(k4 * 4 + kk) * F1 + j];
                #pragma unroll
                for (int nn = 0; nn < 2; nn++) {
                    const float* xa = (const float*)&xr[nn];
                    acc[nn][j] = fmaf(xa[kk], wv, acc[nn][j]);
                }
            }
        }
    }
    #pragma unroll
    for (int nn = 0; nn < 2; nn++) {
        int node = nbase + nn * 256;
        if (node < NN) {
            union { __half2 h2[8]; uint4 u[2]; } pk;
            #pragma unroll
            for (int j = 0; j < 8; j++)
                pk.h2[j] = __floats2half2_rn(acc[nn][2*j], acc[nn][2*j+1]);
            uint4* o = (uint4*)(g_h0s + (long long)node * F1);
            o[0] = pk.u[0];
            o[1] = pk.u[1];
        }
    }
}

// ---------------- single-kernel decoupled-lookback scan --------------------
// also: dinv, cursor copy, rescale h0s by dinv (fp32 math)
#define ST_AGG  (1ull << 62)
#define ST_PRE  (2ull << 62)
__global__ __launch_bounds__(SCAN_T) void k_scan() {
    __shared__ int s_tile;
    __shared__ int wsum[SCAN_T / 32];
    __shared__ int s_pref;
    int t = threadIdx.x, lane = t & 31, wid = t >> 5;

    if (t == 0) s_tile = atomicAdd(&g_cnt.ticket, 1);
    __syncthreads();
    int tile = s_tile;
    int i = tile * SCAN_T + t;

    int v = (i < NN) ? g_cnt.len[i] : 0;
    int s = v;
    #pragma unroll
    for (int off = 1; off < 32; off <<= 1) {
        int n = __shfl_up_sync(0xffffffffu, s, off);
        if (lane >= off) s += n;
    }
    if (lane == 31) wsum[wid] = s;
    __syncthreads();
    if (wid == 0 && lane < SCAN_T / 32) {
        int w = wsum[lane], sc = w;
        #pragma unroll
        for (int off = 1; off < SCAN_T / 32; off <<= 1) {
            int n = __shfl_up_sync(0xffffu, sc, off);
            if (lane >= off) sc += n;
        }
        wsum[lane] = sc - w;
    }
    __syncthreads();
    int incl = s + wsum[wid];                 // inclusive within tile
    __shared__ int s_total;
    if (t == SCAN_T - 1) s_total = incl;
    __syncthreads();
    int total = s_total;

    if (t == 0) {
        if (tile == 0) {
            atomicExch(&g_cnt.state[0], ST_PRE | (unsigned long long)(unsigned)total);
            s_pref = 0;
        } else {
            atomicExch(&g_cnt.state[tile], ST_AGG | (unsigned long long)(unsigned)total);
            int pref = 0;
            for (int tt = tile - 1; tt >= 0; tt--) {
                unsigned long long st;
                do { st = atomicOr(&g_cnt.state[tt], 0ull); } while ((st >> 62) == 0);
                pref += (int)(unsigned)st;
                if ((st >> 62) == 2) break;
            }
            atomicExch(&g_cnt.state[tile],
                       ST_PRE | (unsigned long long)(unsigned)(pref + total));
            s_pref = pref;
        }
    }
    __syncthreads();
    int excl = s_pref + incl - v;

    if (i < NN) {
        g_rowptr[i] = excl;
        g_cursor[i] = excl;
        float di = rsqrtf((float)v + 1.0f);
        g_dinv[i] = di;
        // rescale h0s row by dinv (fp32 math, single extra rounding)
        uint4* row = (uint4*)(g_h0s + (long long)i * F1);
        union { __half2 h2[8]; uint4 u[2]; } pk;
        pk.u[0] = row[0]; pk.u[1] = row[1];
        #pragma unroll
        for (int j = 0; j < 8; j++) {
            float2 f = __half22float2(pk.h2[j]);
            pk.h2[j] = __floats2half2_rn(f.x * di, f.y * di);
        }
        row[0] = pk.u[0]; row[1] = pk.u[1];
        if (i == NN - 1) g_rowptr[NN] = NE;
    }
}

// ---------------- fill CSR (re-read edges; cursor atomics) -----------------
__global__ __launch_bounds__(256) void k_fill(const void* __restrict__ ei) {
    int e = blockIdx.x * 256 + threadIdx.x;
    if (e >= NE) return;
    int r, c;
    if (g_is64) {
        r = ((const int2*)ei)[e].x;
        c = ((const int2*)ei)[NE + e].x;
    } else {
        r = __ldg((const int*)ei + e);
        c = __ldg((const int*)ei + NE + e);
    }
    int slot = atomicAdd(&g_cursor[c], 1);
    g_csr[slot] = r;
}

// ---------------- gather1: warp/node, 16 edges per iteration ---------------
// lane pairs: sub = lane>>1 selects edge, hi = lane&1 selects 16B half of row
__global__ __launch_bounds__(256) void k_gather1(
    const float* __restrict__ b1, const float* __restrict__ W2) {
    int node = (blockIdx.x * blockDim.x + threadIdx.x) >> 5;
    int lane = threadIdx.x & 31;
    if (node >= NN) return;
    int beg = g_rowptr[node];
    int end = g_rowptr[node + 1];
    int sub = lane >> 1;
    int hi  = lane & 1;

    float2 a0 = make_float2(0.f, 0.f), a1 = a0, a2 = a0, a3 = a0;

    for (int base = beg; base < end; base += 16) {
        int idx = base + lane;
        int sv = (lane < 16 && idx < end) ? __ldg(&g_csr[idx]) : 0;
        int src = __shfl_sync(0xffffffffu, sv, sub);
        if (base + sub < end) {
            uint4 u = __ldg((const uint4*)(g_h0s + (long long)src * F1) + hi);
            __half2* h2 = (__half2*)&u;
            float2 f;
            f = __half22float2(h2[0]); a0.x += f.x; a0.y += f.y;
            f = __half22float2(h2[1]); a1.x += f.x; a1.y += f.y;
            f = __half22float2(h2[2]); a2.x += f.x; a2.y += f.y;
            f = __half22float2(h2[3]); a3.x += f.x; a3.y += f.y;
        }
    }
    // reduce over the 16 edge-slots (keep hi split)
    #pragma unroll
    for (int off = 2; off < 32; off <<= 1) {
        a0.x += __shfl_xor_sync(0xffffffffu, a0.x, off);
        a0.y += __shfl_xor_sync(0xffffffffu, a0.y, off);
        a1.x += __shfl_xor_sync(0xffffffffu, a1.x, off);
        a1.y += __shfl_xor_sync(0xffffffffu, a1.y, off);
        a2.x += __shfl_xor_sync(0xffffffffu, a2.x, off);
        a2.y += __shfl_xor_sync(0xffffffffu, a2.y, off);
        a3.x += __shfl_xor_sync(0xffffffffu, a3.x, off);
        a3.y += __shfl_xor_sync(0xffffffffu, a3.y, off);
    }
    // lanes 0,1 now hold feature sums [hi*8, hi*8+8)
    float v = 0.0f;
    float di = __ldg(&g_dinv[node]);
    if (lane < 2) {
        // self loop: + h0s[node] (already dinv[node]-scaled)
        uint4 u = __ldg((const uint4*)(g_h0s + (long long)node * F1) + hi);
        __half2* h2 = (__half2*)&u;
        float2 f;
        f = __half22float2(h2[0]); a0.x += f.x; a0.y += f.y;
        f = __half22float2(h2[1]); a1.x += f.x; a1.y += f.y;
        f = __half22float2(h2[2]); a2.x += f.x; a2.y += f.y;
        f = __half22float2(h2[3]); a3.x += f.x; a3.y += f.y;

        const float* bb = b1 + hi * 8;
        const float* ww = W2 + hi * 8;
        float t0 = fmaxf(fmaf(a0.x, di, __ldg(bb+0)), 0.f) * __ldg(ww+0);
        float t1 = fmaxf(fmaf(a0.y, di, __ldg(bb+1)), 0.f) * __ldg(ww+1);
        float t2 = fmaxf(fmaf(a1.x, di, __ldg(bb+2)), 0.f) * __ldg(ww+2);
        float t3 = fmaxf(fmaf(a1.y, di, __ldg(bb+3)), 0.f) * __ldg(ww+3);
        float t4 = fmaxf(fmaf(a2.x, di, __ldg(bb+4)), 0.f) * __ldg(ww+4);
        float t5 = fmaxf(fmaf(a2.y, di, __ldg(bb+5)), 0.f) * __ldg(ww+5);
        float t6 = fmaxf(fmaf(a3.x, di, __ldg(bb+6)), 0.f) * __ldg(ww+6);
        float t7 = fmaxf(fmaf(a3.y, di, __ldg(bb+7)), 0.f) * __ldg(ww+7);
        v = ((t0 + t1) + (t2 + t3)) + ((t4 + t5) + (t6 + t7));
    }
    v += __shfl_xor_sync(0xffffffffu, v, 1);
    if (lane == 0) g_gs[node] = v * di;
}

// ---------------- gather2: out = sigmoid(dinv*(Σ gs + self) + b2) ----------
__global__ __launch_bounds__(256) void k_gather2(
    const float* __restrict__ b2, float* __restrict__ out) {
    int node = (blockIdx.x * blockDim.x + threadIdx.x) >> 5;
    int lane = threadIdx.x & 31;
    if (node >= NN) return;
    int beg = g_rowptr[node];
    int end = g_rowptr[node + 1];

    float acc = 0.0f;
    int p = beg + lane;
    for (; p + 32 < end; p += 64) {
        int s0 = __ldg(&g_csr[p]);
        int s1 = __ldg(&g_csr[p + 32]);
        acc += __ldg(&g_gs[s0]) + __ldg(&g_gs[s1]);
    }
    if (p < end) acc += __ldg(&g_gs[__ldg(&g_csr[p])]);
    if (lane == 0) acc += __ldg(&g_gs[node]);   // self loop

    acc += __shfl_xor_sync(0xffffffffu, acc, 16);
    acc += __shfl_xor_sync(0xffffffffu, acc, 8);
    acc += __shfl_xor_sync(0xffffffffu, acc, 4);
    acc += __shfl_xor_sync(0xffffffffu, acc, 2);
    acc += __shfl_xor_sync(0xffffffffu, acc, 1);
    if (lane == 0) {
        float v = fmaf(acc, __ldg(&g_dinv[node]), __ldg(&b2[0]));
        out[node] = 1.0f / (1.0f + __expf(-v));
    }
}

// ---------------- launch ----------------------------------------------------
extern "C" void kernel_launch(void* const* d_in, const int* in_sizes, int n_in,
                              void* d_out, int out_size) {
    const float* x  = (const float*)d_in[0];
    const void*  ei = d_in[1];
    const float* W1 = (const float*)d_in[2];
    const float* b1 = (const float*)d_in[3];
    const float* W2 = (const float*)d_in[4];
    const float* b2 = (const float*)d_in[5];
    float* out = (float*)d_out;

    static void* cnt_addr = nullptr;
    static size_t cnt_size = 0;
    if (!cnt_addr) {
        cudaGetSymbolAddress(&cnt_addr, g_cnt);
        cudaGetSymbolSize(&cnt_size, g_cnt);
    }

    cudaMemsetAsync(cnt_addr, 0, cnt_size);
    k_detect<<<1, 32>>>((const unsigned int*)ei);
    k_count_gemm<<<GEMM_BLKS + CNT_BLKS, 256>>>(x, W1, ei);
    k_scan<<<NTILES, SCAN_T>>>();
    k_fill<<<CNT_BLKS, 256>>>(ei);
    k_gather1<<<(NN * 32 + 255) / 256, 256>>>(b1, W2);
    k_gather2<<<(NN * 32 + 255) / 256, 256>>>(b2, out);
}

// round 5
// speedup vs baseline: 1.4255x; 1.0002x over previous
#include <cuda_runtime.h>
#include <cuda_fp16.h>

#define NN 100000
#define NE 3200000
#define F1 16

#define SCAN_T 512
#define NTILES ((NN + SCAN_T - 1) / SCAN_T)   // 196

#define GEMM_BLKS 196                    // 196 * 512 nodes (256 thr * NPT 2)
#define CNT_BLKS (NE / 4 / 256)          // 3125 (4 edges per thread)

// ---- static device scratch (no cudaMalloc allowed) ----
__device__ __half g_h0s[NN * F1];    // (x @ W1) * dinv[node], fp16
__device__ float  g_gs[NN];          // layer-1 output * dinv[node]
__device__ int    g_rowptr[NN + 1];
__device__ int    g_cursor[NN];
__device__ float  g_dinv[NN];
__device__ int    g_csr[NE];         // src grouped by dst
__device__ int    g_is64;

// contiguous so ONE memset clears everything
__device__ struct {
    int len[NN];
    unsigned long long state[NTILES];
    int ticket;
} g_cnt;

// ---------------- dtype detect (int64 vs int32 edge_index) -----------------
__global__ void k_detect(const unsigned int* __restrict__ ei32) {
    if (threadIdx.x == 0) {
        int ok = 1;
        #pragma unroll 1
        for (int k = 0; k < 64; k++)
            if (ei32[2 * k + 1] != 0u) { ok = 0; break; }
        g_is64 = ok;
    }
}

// ---------------- fused: edge counting (4/thread) + GEMM1 ------------------
__global__ __launch_bounds__(256) void k_count_gemm(
    const float* __restrict__ x, const float* __restrict__ W1,
    const void* __restrict__ ei) {
    if (blockIdx.x >= GEMM_BLKS) {
        int base = ((blockIdx.x - GEMM_BLKS) * 256 + threadIdx.x) * 4;
        if (base >= NE) return;
        int c0, c1, c2, c3;
        if (g_is64) {
            const int4* q = (const int4*)ei + NE / 2;   // col half, 2 int64 per int4
            int4 a = __ldg(q + base / 2);
            int4 b = __ldg(q + base / 2 + 1);
            c0 = a.x; c1 = a.z; c2 = b.x; c3 = b.z;
        } else {
            int4 a = __ldg((const int4*)((const int*)ei + NE) + base / 4);
            c0 = a.x; c1 = a.y; c2 = a.z; c3 = a.w;
        }
        atomicAdd(&g_cnt.len[c0], 1);
        atomicAdd(&g_cnt.len[c1], 1);
        atomicAdd(&g_cnt.len[c2], 1);
        atomicAdd(&g_cnt.len[c3], 1);
        return;
    }
    __shared__ float ws[128 * F1];
    for (int t = threadIdx.x; t < 128 * F1; t += 256) ws[t] = W1[t];
    __syncthreads();

    int nbase = blockIdx.x * 512 + threadIdx.x;
    float acc[2][F1];
    #pragma unroll
    for (int nn = 0; nn < 2; nn++)
        #pragma unroll
        for (int j = 0; j < F1; j++) acc[nn][j] = 0.0f;

    #pragma unroll 4
    for (int k4 = 0; k4 < 32; k4++) {
        float4 xr[2];
        #pragma unroll
        for (int nn = 0; nn < 2; nn++) {
            int node = nbase + nn * 256;
            xr[nn] = (node < NN)
                ? __ldg((const float4*)(x + (long long)node * 128) + k4)
                : make_float4(0.f, 0.f, 0.f, 0.f);
        }
        #pragma unroll
        for (int kk = 0; kk < 4; kk++) {
            #pragma unroll
            for (int j = 0; j < F1; j++) {
                float wv = ws[(k4 * 4 + kk) * F1 + j];
                #pragma unroll
                for (int nn = 0; nn < 2; nn++) {
                    const float* xa = (const float*)&xr[nn];
                    acc[nn][j] = fmaf(xa[kk], wv, acc[nn][j]);
                }
            }
        }
    }
    #pragma unroll
    for (int nn = 0; nn < 2; nn++) {
        int node = nbase + nn * 256;
        if (node < NN) {
            union { __half2 h2[8]; uint4 u[2]; } pk;
            #pragma unroll
            for (int j = 0; j < 8; j++)
                pk.h2[j] = __floats2half2_rn(acc[nn][2*j], acc[nn][2*j+1]);
            uint4* o = (uint4*)(g_h0s + (long long)node * F1);
            o[0] = pk.u[0];
            o[1] = pk.u[1];
        }
    }
}

// ---------------- single-kernel decoupled-lookback scan --------------------
#define ST_AGG  (1ull << 62)
#define ST_PRE  (2ull << 62)
__global__ __launch_bounds__(SCAN_T) void k_scan() {
    __shared__ int s_tile;
    __shared__ int wsum[SCAN_T / 32];
    __shared__ int s_pref;
    int t = threadIdx.x, lane = t & 31, wid = t >> 5;

    if (t == 0) s_tile = atomicAdd(&g_cnt.ticket, 1);
    __syncthreads();
    int tile = s_tile;
    int i = tile * SCAN_T + t;

    int v = (i < NN) ? g_cnt.len[i] : 0;
    int s = v;
    #pragma unroll
    for (int off = 1; off < 32; off <<= 1) {
        int n = __shfl_up_sync(0xffffffffu, s, off);
        if (lane >= off) s += n;
    }
    if (lane == 31) wsum[wid] = s;
    __syncthreads();
    if (wid == 0 && lane < SCAN_T / 32) {
        int w = wsum[lane], sc = w;
        #pragma unroll
        for (int off = 1; off < SCAN_T / 32; off <<= 1) {
            int n = __shfl_up_sync(0xffffu, sc, off);
            if (lane >= off) sc += n;
        }
        wsum[lane] = sc - w;
    }
    __syncthreads();
    int incl = s + wsum[wid];
    __shared__ int s_total;
    if (t == SCAN_T - 1) s_total = incl;
    __syncthreads();
    int total = s_total;

    if (t == 0) {
        if (tile == 0) {
            atomicExch(&g_cnt.state[0], ST_PRE | (unsigned long long)(unsigned)total);
            s_pref = 0;
        } else {
            atomicExch(&g_cnt.state[tile], ST_AGG | (unsigned long long)(unsigned)total);
            int pref = 0;
            for (int tt = tile - 1; tt >= 0; tt--) {
                unsigned long long st;
                do { st = atomicOr(&g_cnt.state[tt], 0ull); } while ((st >> 62) == 0);
                pref += (int)(unsigned)st;
                if ((st >> 62) == 2) break;
            }
            atomicExch(&g_cnt.state[tile],
                       ST_PRE | (unsigned long long)(unsigned)(pref + total));
            s_pref = pref;
        }
    }
    __syncthreads();
    int excl = s_pref + incl - v;

    if (i < NN) {
        g_rowptr[i] = excl;
        g_cursor[i] = excl;
        float di = rsqrtf((float)v + 1.0f);
        g_dinv[i] = di;
        uint4* row = (uint4*)(g_h0s + (long long)i * F1);
        union { __half2 h2[8]; uint4 u[2]; } pk;
        pk.u[0] = row[0]; pk.u[1] = row[1];
        #pragma unroll
        for (int j = 0; j < 8; j++) {
            float2 f = __half22float2(pk.h2[j]);
            pk.h2[j] = __floats2half2_rn(f.x * di, f.y * di);
        }
        row[0] = pk.u[0]; row[1] = pk.u[1];
        if (i == NN - 1) g_rowptr[NN] = NE;
    }
}

// ---------------- fill CSR: 4 edges/thread, batched atomics ----------------
__global__ __launch_bounds__(256) void k_fill(const void* __restrict__ ei) {
    int base = (blockIdx.x * 256 + threadIdx.x) * 4;
    if (base >= NE) return;
    int r0, r1, r2, r3, c0, c1, c2, c3;
    if (g_is64) {
        const int4* p = (const int4*)ei;                // row half
        const int4* q = (const int4*)ei + NE / 2;       // col half
        int4 a = __ldg(p + base / 2);
        int4 b = __ldg(p + base / 2 + 1);
        int4 d = __ldg(q + base / 2);
        int4 e = __ldg(q + base / 2 + 1);
        r0 = a.x; r1 = a.z; r2 = b.x; r3 = b.z;
        c0 = d.x; c1 = d.z; c2 = e.x; c3 = e.z;
    } else {
        int4 a = __ldg((const int4*)((const int*)ei) + base / 4);
        int4 d = __ldg((const int4*)((const int*)ei + NE) + base / 4);
        r0 = a.x; r1 = a.y; r2 = a.z; r3 = a.w;
        c0 = d.x; c1 = d.y; c2 = d.z; c3 = d.w;
    }
    int s0 = atomicAdd(&g_cursor[c0], 1);
    int s1 = atomicAdd(&g_cursor[c1], 1);
    int s2 = atomicAdd(&g_cursor[c2], 1);
    int s3 = atomicAdd(&g_cursor[c3], 1);
    g_csr[s0] = r0;
    g_csr[s1] = r1;
    g_csr[s2] = r2;
    g_csr[s3] = r3;
}

// ---------------- gather1: warp/node, 16 edges per iteration ---------------
__global__ __launch_bounds__(256) void k_gather1(
    const float* __restrict__ b1, const float* __restrict__ W2) {
    int node = (blockIdx.x * blockDim.x + threadIdx.x) >> 5;
    int lane = threadIdx.x & 31;
    if (node >= NN) return;
    int beg = g_rowptr[node];
    int end = g_rowptr[node + 1];
    int sub = lane >> 1;
    int hi  = lane & 1;

    float2 a0 = make_float2(0.f, 0.f), a1 = a0, a2 = a0, a3 = a0;

    for (int base = beg; base < end; base += 16) {
        int idx = base + lane;
        int sv = (lane < 16 && idx < end) ? __ldg(&g_csr[idx]) : 0;
        int src = __shfl_sync(0xffffffffu, sv, sub);
        if (base + sub < end) {
            uint4 u = __ldg((const uint4*)(g_h0s + (long long)src * F1) + hi);
            __half2* h2 = (__half2*)&u;
            float2 f;
            f = __half22float2(h2[0]); a0.x += f.x; a0.y += f.y;
            f = __half22float2(h2[1]); a1.x += f.x; a1.y += f.y;
            f = __half22float2(h2[2]); a2.x += f.x; a2.y += f.y;
            f = __half22float2(h2[3]); a3.x += f.x; a3.y += f.y;
        }
    }
    #pragma unroll
    for (int off = 2; off < 32; off <<= 1) {
        a0.x += __shfl_xor_sync(0xffffffffu, a0.x, off);
        a0.y += __shfl_xor_sync(0xffffffffu, a0.y, off);
        a1.x += __shfl_xor_sync(0xffffffffu, a1.x, off);
        a1.y += __shfl_xor_sync(0xffffffffu, a1.y, off);
        a2.x += __shfl_xor_sync(0xffffffffu, a2.x, off);
        a2.y += __shfl_xor_sync(0xffffffffu, a2.y, off);
        a3.x += __shfl_xor_sync(0xffffffffu, a3.x, off);
        a3.y += __shfl_xor_sync(0xffffffffu, a3.y, off);
    }
    float v = 0.0f;
    float di = __ldg(&g_dinv[node]);
    if (lane < 2) {
        uint4 u = __ldg((const uint4*)(g_h0s + (long long)node * F1) + hi);
        __half2* h2 = (__half2*)&u;
        float2 f;
        f = __half22float2(h2[0]); a0.x += f.x; a0.y += f.y;
        f = __half22float2(h2[1]); a1.x += f.x; a1.y += f.y;
        f = __half22float2(h2[2]); a2.x += f.x; a2.y += f.y;
        f = __half22float2(h2[3]); a3.x += f.x; a3.y += f.y;

        const float* bb = b1 + hi * 8;
        const float* ww = W2 + hi * 8;
        float t0 = fmaxf(fmaf(a0.x, di, __ldg(bb+0)), 0.f) * __ldg(ww+0);
        float t1 = fmaxf(fmaf(a0.y, di, __ldg(bb+1)), 0.f) * __ldg(ww+1);
        float t2 = fmaxf(fmaf(a1.x, di, __ldg(bb+2)), 0.f) * __ldg(ww+2);
        float t3 = fmaxf(fmaf(a1.y, di, __ldg(bb+3)), 0.f) * __ldg(ww+3);
        float t4 = fmaxf(fmaf(a2.x, di, __ldg(bb+4)), 0.f) * __ldg(ww+4);
        float t5 = fmaxf(fmaf(a2.y, di, __ldg(bb+5)), 0.f) * __ldg(ww+5);
        float t6 = fmaxf(fmaf(a3.x, di, __ldg(bb+6)), 0.f) * __ldg(ww+6);
        float t7 = fmaxf(fmaf(a3.y, di, __ldg(bb+7)), 0.f) * __ldg(ww+7);
        v = ((t0 + t1) + (t2 + t3)) + ((t4 + t5) + (t6 + t7));
    }
    v += __shfl_xor_sync(0xffffffffu, v, 1);
    if (lane == 0) g_gs[node] = v * di;
}

// ---------------- gather2: out = sigmoid(dinv*(Σ gs + self) + b2) ----------
__global__ __launch_bounds__(256) void k_gather2(
    const float* __restrict__ b2, float* __restrict__ out) {
    int node = (blockIdx.x * blockDim.x + threadIdx.x) >> 5;
    int lane = threadIdx.x & 31;
    if (node >= NN) return;
    int beg = g_rowptr[node];
    int end = g_rowptr[node + 1];

    float acc = 0.0f;
    int p = beg + lane;
    for (; p + 32 < end; p += 64) {
        int s0 = __ldg(&g_csr[p]);
        int s1 = __ldg(&g_csr[p + 32]);
        acc += __ldg(&g_gs[s0]) + __ldg(&g_gs[s1]);
    }
    if (p < end) acc += __ldg(&g_gs[__ldg(&g_csr[p])]);
    if (lane == 0) acc += __ldg(&g_gs[node]);   // self loop

    acc += __shfl_xor_sync(0xffffffffu, acc, 16);
    acc += __shfl_xor_sync(0xffffffffu, acc, 8);
    acc += __shfl_xor_sync(0xffffffffu, acc, 4);
    acc += __shfl_xor_sync(0xffffffffu, acc, 2);
    acc += __shfl_xor_sync(0xffffffffu, acc, 1);
    if (lane == 0) {
        float v = fmaf(acc, __ldg(&g_dinv[node]), __ldg(&b2[0]));
        out[node] = 1.0f / (1.0f + __expf(-v));
    }
}

// ---------------- launch ----------------------------------------------------
extern "C" void kernel_launch(void* const* d_in, const int* in_sizes, int n_in,
                              void* d_out, int out_size) {
    const float* x  = (const float*)d_in[0];
    const void*  ei = d_in[1];
    const float* W1 = (const float*)d_in[2];
    const float* b1 = (const float*)d_in[3];
    const float* W2 = (const float*)d_in[4];
    const float* b2 = (const float*)d_in[5];
    float* out = (float*)d_out;

    static void* cnt_addr = nullptr;
    static size_t cnt_size = 0;
    if (!cnt_addr) {
        cudaGetSymbolAddress(&cnt_addr, g_cnt);
        cudaGetSymbolSize(&cnt_size, g_cnt);
    }

    cudaMemsetAsync(cnt_addr, 0, cnt_size);
    k_detect<<<1, 32>>>((const unsigned int*)ei);
    k_count_gemm<<<GEMM_BLKS + CNT_BLKS, 256>>>(x, W1, ei);
    k_scan<<<NTILES, SCAN_T>>>();
    k_fill<<<NE / 4 / 256, 256>>>(ei);
    k_gather1<<<(NN * 32 + 255) / 256, 256>>>(b1, W2);
    k_gather2<<<(NN * 32 + 255) / 256, 256>>>(b2, out);
}

// round 6
// speedup vs baseline: 1.8391x; 1.2901x over previous
#include <cuda_runtime.h>
#include <cuda_fp16.h>

#define NN 100000
#define NE 3200000
#define F1 16
#define CAP 96                       // slots per node (Poisson(32): overflow ~0)
#define OVF_MAX (1 << 20)

#define GEMM_BLKS 196                // 196 * 512 nodes
#define FILL_BLKS (NE / 4 / 256)     // 3125 (4 edges per thread)

// ---- static device scratch (no cudaMalloc allowed) ----
__device__ __half g_h0s[NN * F1];    // (x @ W1) [* dinv after k_scale], fp16
__device__ float  g_gs[NN];          // layer-1 output * dinv[node]
__device__ float  g_dinv[NN];
__device__ int    g_csr[NN * CAP];   // padded bins: src, grouped by dst
__device__ int    g_is64;

// zeroed each launch with ONE memset (prefix only)
__device__ struct {
    int cursor[NN];
    int ovf_cnt;
    int2 ovf[OVF_MAX];               // NOT memset (only first ovf_cnt valid)
} g_dyn;

// ---------------- dtype detect (int64 vs int32 edge_index) -----------------
__global__ void k_detect(const unsigned int* __restrict__ ei32) {
    if (threadIdx.x == 0) {
        int ok = 1;
        #pragma unroll 1
        for (int k = 0; k < 64; k++)
            if (ei32[2 * k + 1] != 0u) { ok = 0; break; }
        g_is64 = ok;
    }
}

// ---------------- fused: GEMM1 + CSR bin-fill (independent work) -----------
__global__ __launch_bounds__(256) void k_fill_gemm(
    const float* __restrict__ x, const float* __restrict__ W1,
    const void* __restrict__ ei) {
    if (blockIdx.x >= GEMM_BLKS) {
        // ---- fill: 4 edges/thread ----
        int base = ((blockIdx.x - GEMM_BLKS) * 256 + threadIdx.x) * 4;
        int r[4], c[4];
        if (g_is64) {
            const int4* p = (const int4*)ei;            // row half
            const int4* q = (const int4*)ei + NE / 2;   // col half
            int4 a = __ldg(p + base / 2);
            int4 b = __ldg(p + base / 2 + 1);
            int4 d = __ldg(q + base / 2);
            int4 e = __ldg(q + base / 2 + 1);
            r[0] = a.x; r[1] = a.z; r[2] = b.x; r[3] = b.z;
            c[0] = d.x; c[1] = d.z; c[2] = e.x; c[3] = e.z;
        } else {
            int4 a = __ldg((const int4*)((const int*)ei) + base / 4);
            int4 d = __ldg((const int4*)((const int*)ei + NE) + base / 4);
            r[0] = a.x; r[1] = a.y; r[2] = a.z; r[3] = a.w;
            c[0] = d.x; c[1] = d.y; c[2] = d.z; c[3] = d.w;
        }
        int s[4];
        #pragma unroll
        for (int j = 0; j < 4; j++) s[j] = atomicAdd(&g_dyn.cursor[c[j]], 1);
        #pragma unroll
        for (int j = 0; j < 4; j++) {
            if (s[j] < CAP) {
                g_csr[c[j] * CAP + s[j]] = r[j];
            } else {                      // guaranteed-correct spill path
                int o = atomicAdd(&g_dyn.ovf_cnt, 1);
                if (o < OVF_MAX) g_dyn.ovf[o] = make_int2(r[j], c[j]);
            }
        }
        return;
    }
    // ---- GEMM: h0s = fp16(x @ W1), unscaled ----
    __shared__ float ws[128 * F1];
    for (int t = threadIdx.x; t < 128 * F1; t += 256) ws[t] = W1[t];
    __syncthreads();

    int nbase = blockIdx.x * 512 + threadIdx.x;
    float acc[2][F1];
    #pragma unroll
    for (int nn = 0; nn < 2; nn++)
        #pragma unroll
        for (int j = 0; j < F1; j++) acc[nn][j] = 0.0f;

    #pragma unroll 4
    for (int k4 = 0; k4 < 32; k4++) {
        float4 xr[2];
        #pragma unroll
        for (int nn = 0; nn < 2; nn++) {
            int node = nbase + nn * 256;
            xr[nn] = (node < NN)
                ? __ldg((const float4*)(x + (long long)node * 128) + k4)
                : make_float4(0.f, 0.f, 0.f, 0.f);
        }
        #pragma unroll
        for (int kk = 0; kk < 4; kk++) {
            #pragma unroll
            for (int j = 0; j < F1; j++) {
                float wv = ws[(k4 * 4 + kk) * F1 + j];
                #pragma unroll
                for (int nn = 0; nn < 2; nn++) {
                    const float* xa = (const float*)&xr[nn];
                    acc[nn][j] = fmaf(xa[kk], wv, acc[nn][j]);
                }
            }
        }
    }
    #pragma unroll
    for (int nn = 0; nn < 2; nn++) {
        int node = nbase + nn * 256;
        if (node < NN) {
            union { __half2 h2[8]; uint4 u[2]; } pk;
            #pragma unroll
            for (int j = 0; j < 8; j++)
                pk.h2[j] = __floats2half2_rn(acc[nn][2*j], acc[nn][2*j+1]);
            uint4* o = (uint4*)(g_h0s + (long long)node * F1);
            o[0] = pk.u[0];
            o[1] = pk.u[1];
        }
    }
}

// ---------------- scale: dinv from cursor counts; h0s *= dinv --------------
__global__ __launch_bounds__(256) void k_scale() {
    int i = blockIdx.x * 256 + threadIdx.x;
    if (i >= NN) return;
    int cnt = g_dyn.cursor[i];
    float di = rsqrtf((float)cnt + 1.0f);
    g_dinv[i] = di;
    uint4* row = (uint4*)(g_h0s + (long long)i * F1);
    union { __half2 h2[8]; uint4 u[2]; } pk;
    pk.u[0] = row[0]; pk.u[1] = row[1];
    #pragma unroll
    for (int j = 0; j < 8; j++) {
        float2 f = __half22float2(pk.h2[j]);
        pk.h2[j] = __floats2half2_rn(f.x * di, f.y * di);
    }
    row[0] = pk.u[0]; row[1] = pk.u[1];
}

// ---------------- gather1: warp/node, 16 edges per iteration ---------------
// lane pairs: sub = lane>>1 selects edge, hi = lane&1 selects 16B half of row
__global__ __launch_bounds__(256) void k_gather1(
    const float* __restrict__ b1, const float* __restrict__ W2) {
    int node = (blockIdx.x * blockDim.x + threadIdx.x) >> 5;
    int lane = threadIdx.x & 31;
    if (node >= NN) return;
    int cnt = g_dyn.cursor[node];
    int len = min(cnt, CAP);
    int beg = node * CAP;
    int end = beg + len;
    int sub = lane >> 1;
    int hi  = lane & 1;

    float2 a0 = make_float2(0.f, 0.f), a1 = a0, a2 = a0, a3 = a0;

    for (int base = beg; base < end; base += 16) {
        int idx = base + lane;
        int sv = (lane < 16 && idx < end) ? __ldg(&g_csr[idx]) : 0;
        int src = __shfl_sync(0xffffffffu, sv, sub);
        if (base + sub < end) {
            uint4 u = __ldg((const uint4*)(g_h0s + (long long)src * F1) + hi);
            __half2* h2 = (__half2*)&u;
            float2 f;
            f = __half22float2(h2[0]); a0.x += f.x; a0.y += f.y;
            f = __half22float2(h2[1]); a1.x += f.x; a1.y += f.y;
            f = __half22float2(h2[2]); a2.x += f.x; a2.y += f.y;
            f = __half22float2(h2[3]); a3.x += f.x; a3.y += f.y;
        }
    }
    #pragma unroll
    for (int off = 2; off < 32; off <<= 1) {
        a0.x += __shfl_xor_sync(0xffffffffu, a0.x, off);
        a0.y += __shfl_xor_sync(0xffffffffu, a0.y, off);
        a1.x += __shfl_xor_sync(0xffffffffu, a1.x, off);
        a1.y += __shfl_xor_sync(0xffffffffu, a1.y, off);
        a2.x += __shfl_xor_sync(0xffffffffu, a2.x, off);
        a2.y += __shfl_xor_sync(0xffffffffu, a2.y, off);
        a3.x += __shfl_xor_sync(0xffffffffu, a3.x, off);
        a3.y += __shfl_xor_sync(0xffffffffu, a3.y, off);
    }
    float v = 0.0f;
    float di = __ldg(&g_dinv[node]);
    if (lane < 2) {
        // self loop (h0s already dinv-scaled)
        uint4 u = __ldg((const uint4*)(g_h0s + (long long)node * F1) + hi);
        __half2* h2 = (__half2*)&u;
        float2 f;
        f = __half22float2(h2[0]); a0.x += f.x; a0.y += f.y;
        f = __half22float2(h2[1]); a1.x += f.x; a1.y += f.y;
        f = __half22float2(h2[2]); a2.x += f.x; a2.y += f.y;
        f = __half22float2(h2[3]); a3.x += f.x; a3.y += f.y;

        if (cnt > CAP) {    // overflow path (never taken for this input)
            int no = min(g_dyn.ovf_cnt, OVF_MAX);
            for (int o = 0; o < no; o++) {
                int2 rc = g_dyn.ovf[o];
                if (rc.y == node) {
                    uint4 uu = __ldg((const uint4*)(g_h0s + (long long)rc.x * F1) + hi);
                    __half2* hh = (__half2*)&uu;
                    float2 ff;
                    ff = __half22float2(hh[0]); a0.x += ff.x; a0.y += ff.y;
                    ff = __half22float2(hh[1]); a1.x += ff.x; a1.y += ff.y;
                    ff = __half22float2(hh[2]); a2.x += ff.x; a2.y += ff.y;
                    ff = __half22float2(hh[3]); a3.x += ff.x; a3.y += ff.y;
                }
            }
        }

        const float* bb = b1 + hi * 8;
        const float* ww = W2 + hi * 8;
        float t0 = fmaxf(fmaf(a0.x, di, __ldg(bb+0)), 0.f) * __ldg(ww+0);
        float t1 = fmaxf(fmaf(a0.y, di, __ldg(bb+1)), 0.f) * __ldg(ww+1);
        float t2 = fmaxf(fmaf(a1.x, di, __ldg(bb+2)), 0.f) * __ldg(ww+2);
        float t3 = fmaxf(fmaf(a1.y, di, __ldg(bb+3)), 0.f) * __ldg(ww+3);
        float t4 = fmaxf(fmaf(a2.x, di, __ldg(bb+4)), 0.f) * __ldg(ww+4);
        float t5 = fmaxf(fmaf(a2.y, di, __ldg(bb+5)), 0.f) * __ldg(ww+5);
        float t6 = fmaxf(fmaf(a3.x, di, __ldg(bb+6)), 0.f) * __ldg(ww+6);
        float t7 = fmaxf(fmaf(a3.y, di, __ldg(bb+7)), 0.f) * __ldg(ww+7);
        v = ((t0 + t1) + (t2 + t3)) + ((t4 + t5) + (t6 + t7));
    }
    v += __shfl_xor_sync(0xffffffffu, v, 1);
    if (lane == 0) g_gs[node] = v * di;
}

// ---------------- gather2: out = sigmoid(dinv*(Σ gs + self) + b2) ----------
__global__ __launch_bounds__(256) void k_gather2(
    const float* __restrict__ b2, float* __restrict__ out) {
    int node = (blockIdx.x * blockDim.x + threadIdx.x) >> 5;
    int lane = threadIdx.x & 31;
    if (node >= NN) return;
    int cnt = g_dyn.cursor[node];
    int len = min(cnt, CAP);
    int beg = node * CAP;
    int end = beg + len;

    float acc = 0.0f;
    int p = beg + lane;
    for (; p + 32 < end; p += 64) {
        int s0 = __ldg(&g_csr[p]);
        int s1 = __ldg(&g_csr[p + 32]);
        acc += __ldg(&g_gs[s0]) + __ldg(&g_gs[s1]);
    }
    if (p < end) acc += __ldg(&g_gs[__ldg(&g_csr[p])]);
    if (lane == 0) {
        acc += __ldg(&g_gs[node]);   // self loop
        if (cnt > CAP) {             // overflow path (never taken here)
            int no = min(g_dyn.ovf_cnt, OVF_MAX);
            for (int o = 0; o < no; o++) {
                int2 rc = g_dyn.ovf[o];
                if (rc.y == node) acc += __ldg(&g_gs[rc.x]);
            }
        }
    }

    acc += __shfl_xor_sync(0xffffffffu, acc, 16);
    acc += __shfl_xor_sync(0xffffffffu, acc, 8);
    acc += __shfl_xor_sync(0xffffffffu, acc, 4);
    acc += __shfl_xor_sync(0xffffffffu, acc, 2);
    acc += __shfl_xor_sync(0xffffffffu, acc, 1);
    if (lane == 0) {
        float v = fmaf(acc, __ldg(&g_dinv[node]), __ldg(&b2[0]));
        out[node] = 1.0f / (1.0f + __expf(-v));
    }
}

// ---------------- launch ----------------------------------------------------
extern "C" void kernel_launch(void* const* d_in, const int* in_sizes, int n_in,
                              void* d_out, int out_size) {
    const float* x  = (const float*)d_in[0];
    const void*  ei = d_in[1];
    const float* W1 = (const float*)d_in[2];
    const float* b1 = (const float*)d_in[3];
    const float* W2 = (const float*)d_in[4];
    const float* b2 = (const float*)d_in[5];
    float* out = (float*)d_out;

    static void* dyn_addr = nullptr;
    if (!dyn_addr) cudaGetSymbolAddress(&dyn_addr, g_dyn);

    // zero cursors + ovf_cnt only (prefix of g_dyn)
    cudaMemsetAsync(dyn_addr, 0, (size_t)(NN + 1) * sizeof(int));
    k_detect<<<1, 32>>>((const unsigned int*)ei);
    k_fill_gemm<<<GEMM_BLKS + FILL_BLKS, 256>>>(x, W1, ei);
    k_scale<<<(NN + 255) / 256, 256>>>();
    k_gather1<<<(NN * 32 + 255) / 256, 256>>>(b1, W2);
    k_gather2<<<(NN * 32 + 255) / 256, 256>>>(b2, out);
}

// round 7
// speedup vs baseline: 1.9753x; 1.0741x over previous
#include <cuda_runtime.h>
#include <cuda_fp16.h>

#define NN 100000
#define NE 3200000
#define F1 16
#define CAP 96                       // slots per node (Poisson(32): overflow ~0)
#define OVF_MAX (1 << 20)

#define GEMM_BLKS 196                // 196 * 512 nodes
#define FILL_BLKS (NE / 4 / 256)     // 3125 (4 edges per thread)

// ---- static device scratch (no cudaMalloc allowed) ----
__device__ float  g_h0f[NN * F1];    // (x @ W1) [* dinv after k_scale], fp32
__device__ float  g_gs[NN];          // layer-1 output * dinv[node]
__device__ float  g_dinv[NN];
__device__ int    g_csr[NN * CAP];   // padded bins: src, grouped by dst
__device__ int    g_is64;

// zeroed each launch with ONE memset (prefix only)
__device__ struct {
    int cursor[NN];
    int ovf_cnt;
    int2 ovf[OVF_MAX];               // NOT memset (only first ovf_cnt valid)
} g_dyn;

// ---------------- dtype detect (int64 vs int32 edge_index) -----------------
__global__ void k_detect(const unsigned int* __restrict__ ei32) {
    if (threadIdx.x == 0) {
        int ok = 1;
        #pragma unroll 1
        for (int k = 0; k < 64; k++)
            if (ei32[2 * k + 1] != 0u) { ok = 0; break; }
        g_is64 = ok;
    }
}

// ---------------- fused: GEMM1 + CSR bin-fill (independent work) -----------
__global__ __launch_bounds__(256) void k_fill_gemm(
    const float* __restrict__ x, const float* __restrict__ W1,
    const void* __restrict__ ei) {
    if (blockIdx.x >= GEMM_BLKS) {
        // ---- fill: 4 edges/thread ----
        int base = ((blockIdx.x - GEMM_BLKS) * 256 + threadIdx.x) * 4;
        int r[4], c[4];
        if (g_is64) {
            const int4* p = (const int4*)ei;            // row half
            const int4* q = (const int4*)ei + NE / 2;   // col half
            int4 a = __ldg(p + base / 2);
            int4 b = __ldg(p + base / 2 + 1);
            int4 d = __ldg(q + base / 2);
            int4 e = __ldg(q + base / 2 + 1);
            r[0] = a.x; r[1] = a.z; r[2] = b.x; r[3] = b.z;
            c[0] = d.x; c[1] = d.z; c[2] = e.x; c[3] = e.z;
        } else {
            int4 a = __ldg((const int4*)((const int*)ei) + base / 4);
            int4 d = __ldg((const int4*)((const int*)ei + NE) + base / 4);
            r[0] = a.x; r[1] = a.y; r[2] = a.z; r[3] = a.w;
            c[0] = d.x; c[1] = d.y; c[2] = d.z; c[3] = d.w;
        }
        int s[4];
        #pragma unroll
        for (int j = 0; j < 4; j++) s[j] = atomicAdd(&g_dyn.cursor[c[j]], 1);
        #pragma unroll
        for (int j = 0; j < 4; j++) {
            if (s[j] < CAP) {
                g_csr[c[j] * CAP + s[j]] = r[j];
            } else {                      // guaranteed-correct spill path
                int o = atomicAdd(&g_dyn.ovf_cnt, 1);
                if (o < OVF_MAX) g_dyn.ovf[o] = make_int2(r[j], c[j]);
            }
        }
        return;
    }
    // ---- GEMM: h0f = x @ W1, fp32, unscaled ----
    __shared__ float ws[128 * F1];
    for (int t = threadIdx.x; t < 128 * F1; t += 256) ws[t] = W1[t];
    __syncthreads();

    int nbase = blockIdx.x * 512 + threadIdx.x;
    float acc[2][F1];
    #pragma unroll
    for (int nn = 0; nn < 2; nn++)
        #pragma unroll
        for (int j = 0; j < F1; j++) acc[nn][j] = 0.0f;

    #pragma unroll 4
    for (int k4 = 0; k4 < 32; k4++) {
        float4 xr[2];
        #pragma unroll
        for (int nn = 0; nn < 2; nn++) {
            int node = nbase + nn * 256;
            xr[nn] = (node < NN)
                ? __ldg((const float4*)(x + (long long)node * 128) + k4)
                : make_float4(0.f, 0.f, 0.f, 0.f);
        }
        #pragma unroll
        for (int kk = 0; kk < 4; kk++) {
            #pragma unroll
            for (int j = 0; j < F1; j++) {
                float wv = ws[(k4 * 4 + kk) * F1 + j];
                #pragma unroll
                for (int nn = 0; nn < 2; nn++) {
                    const float* xa = (const float*)&xr[nn];
                    acc[nn][j] = fmaf(xa[kk], wv, acc[nn][j]);
                }
            }
        }
    }
    #pragma unroll
    for (int nn = 0; nn < 2; nn++) {
        int node = nbase + nn * 256;
        if (node < NN) {
            float4* o = (float4*)(g_h0f + (long long)node * F1);
            o[0] = make_float4(acc[nn][0], acc[nn][1], acc[nn][2], acc[nn][3]);
            o[1] = make_float4(acc[nn][4], acc[nn][5], acc[nn][6], acc[nn][7]);
            o[2] = make_float4(acc[nn][8], acc[nn][9], acc[nn][10], acc[nn][11]);
            o[3] = make_float4(acc[nn][12], acc[nn][13], acc[nn][14], acc[nn][15]);
        }
    }
}

// ---------------- scale: dinv from cursor counts; h0f *= dinv --------------
__global__ __launch_bounds__(256) void k_scale() {
    int i = blockIdx.x * 256 + threadIdx.x;
    if (i >= NN) return;
    int cnt = g_dyn.cursor[i];
    float di = rsqrtf((float)cnt + 1.0f);
    g_dinv[i] = di;
    float4* row = (float4*)(g_h0f + (long long)i * F1);
    #pragma unroll
    for (int j = 0; j < 4; j++) {
        float4 v = row[j];
        row[j] = make_float4(v.x * di, v.y * di, v.z * di, v.w * di);
    }
}

// ---------------- gather1: warp/node, 4 lanes/edge, float4 -----------------
// q = lane>>2 selects edge slot (8 per iter), f4 = lane&3 selects 16B quarter
__global__ __launch_bounds__(256) void k_gather1(
    const float* __restrict__ b1, const float* __restrict__ W2) {
    int node = (blockIdx.x * blockDim.x + threadIdx.x) >> 5;
    int lane = threadIdx.x & 31;
    if (node >= NN) return;
    int cnt = g_dyn.cursor[node];
    int len = min(cnt, CAP);
    int beg = node * CAP;
    int end = beg + len;
    int q  = lane >> 2;
    int f4 = lane & 3;

    // init with self-loop (h0f already dinv-scaled) on edge-slot 0
    float4 acc = make_float4(0.f, 0.f, 0.f, 0.f);
    if (q == 0)
        acc = __ldg((const float4*)(g_h0f + (long long)node * F1) + f4);

    for (int p = beg; p < end; p += 8) {
        int idx = p + q;
        if (idx < end) {
            int src = __ldg(&g_csr[idx]);
            float4 v = __ldg((const float4*)(g_h0f + (long long)src * F1) + f4);
            acc.x += v.x; acc.y += v.y; acc.z += v.z; acc.w += v.w;
        }
    }
    // reduce across the 8 edge-slots (keep f4 split)
    #pragma unroll
    for (int off = 4; off < 32; off <<= 1) {
        acc.x += __shfl_xor_sync(0xffffffffu, acc.x, off);
        acc.y += __shfl_xor_sync(0xffffffffu, acc.y, off);
        acc.z += __shfl_xor_sync(0xffffffffu, acc.z, off);
        acc.w += __shfl_xor_sync(0xffffffffu, acc.w, off);
    }
    float di = __ldg(&g_dinv[node]);
    float v = 0.0f;
    if (lane < 4) {
        if (cnt > CAP) {    // overflow path (never taken for this input)
            int no = min(g_dyn.ovf_cnt, OVF_MAX);
            for (int o = 0; o < no; o++) {
                int2 rc = g_dyn.ovf[o];
                if (rc.y == node) {
                    float4 u = __ldg((const float4*)(g_h0f + (long long)rc.x * F1) + f4);
                    acc.x += u.x; acc.y += u.y; acc.z += u.z; acc.w += u.w;
                }
            }
        }
        float4 bb = __ldg((const float4*)b1 + lane);
        float4 ww = __ldg((const float4*)W2 + lane);
        float t0 = fmaxf(fmaf(acc.x, di, bb.x), 0.f) * ww.x;
        float t1 = fmaxf(fmaf(acc.y, di, bb.y), 0.f) * ww.y;
        float t2 = fmaxf(fmaf(acc.z, di, bb.z), 0.f) * ww.z;
        float t3 = fmaxf(fmaf(acc.w, di, bb.w), 0.f) * ww.w;
        v = (t0 + t1) + (t2 + t3);
    }
    v += __shfl_xor_sync(0xffffffffu, v, 1);
    v += __shfl_xor_sync(0xffffffffu, v, 2);
    if (lane == 0) g_gs[node] = v * di;
}

// ---------------- gather2: out = sigmoid(dinv*(Σ gs + self) + b2) ----------
__global__ __launch_bounds__(256) void k_gather2(
    const float* __restrict__ b2, float* __restrict__ out) {
    int node = (blockIdx.x * blockDim.x + threadIdx.x) >> 5;
    int lane = threadIdx.x & 31;
    if (node >= NN) return;
    int cnt = g_dyn.cursor[node];
    int len = min(cnt, CAP);
    int beg = node * CAP;
    int end = beg + len;

    float acc = 0.0f;
    int p = beg + lane;
    for (; p + 32 < end; p += 64) {
        int s0 = __ldg(&g_csr[p]);
        int s1 = __ldg(&g_csr[p + 32]);
        acc += __ldg(&g_gs[s0]) + __ldg(&g_gs[s1]);
    }
    if (p < end) acc += __ldg(&g_gs[__ldg(&g_csr[p])]);
    if (lane == 0) {
        acc += __ldg(&g_gs[node]);   // self loop
        if (cnt > CAP) {             // overflow path (never taken here)
            int no = min(g_dyn.ovf_cnt, OVF_MAX);
            for (int o = 0; o < no; o++) {
                int2 rc = g_dyn.ovf[o];
                if (rc.y == node) acc += __ldg(&g_gs[rc.x]);
            }
        }
    }

    acc += __shfl_xor_sync(0xffffffffu, acc, 16);
    acc += __shfl_xor_sync(0xffffffffu, acc, 8);
    acc += __shfl_xor_sync(0xffffffffu, acc, 4);
    acc += __shfl_xor_sync(0xffffffffu, acc, 2);
    acc += __shfl_xor_sync(0xffffffffu, acc, 1);
    if (lane == 0) {
        float v = fmaf(acc, __ldg(&g_dinv[node]), __ldg(&b2[0]));
        out[node] = 1.0f / (1.0f + __expf(-v));
    }
}

// ---------------- launch ----------------------------------------------------
extern "C" void kernel_launch(void* const* d_in, const int* in_sizes, int n_in,
                              void* d_out, int out_size) {
    const float* x  = (const float*)d_in[0];
    const void*  ei = d_in[1];
    const float* W1 = (const float*)d_in[2];
    const float* b1 = (const float*)d_in[3];
    const float* W2 = (const float*)d_in[4];
    const float* b2 = (const float*)d_in[5];
    float* out = (float*)d_out;

    static void* dyn_addr = nullptr;
    if (!dyn_addr) cudaGetSymbolAddress(&dyn_addr, g_dyn);

    // zero cursors + ovf_cnt only (prefix of g_dyn)
    cudaMemsetAsync(dyn_addr, 0, (size_t)(NN + 1) * sizeof(int));
    k_detect<<<1, 32>>>((const unsigned int*)ei);
    k_fill_gemm<<<GEMM_BLKS + FILL_BLKS, 256>>>(x, W1, ei);
    k_scale<<<(NN + 255) / 256, 256>>>();
    k_gather1<<<(NN * 32 + 255) / 256, 256>>>(b1, W2);
    k_gather2<<<(NN * 32 + 255) / 256, 256>>>(b2, out);
}